// round 1
// baseline (speedup 1.0000x reference)
#include <cuda_runtime.h>
#include <math.h>

#define BB 4
#define SS 2048
#define HH 16
#define DD 128
#define DH 64    // effective qk dim (first half, duplicated in reference)
#define BM 64
#define BN 64

// Scratch (no allocations allowed): head-major preprocessed tensors.
__device__ float g_Qp[BB*HH*SS*DH];   // 33.5 MB
__device__ float g_Kp[BB*HH*SS*DH];   // 33.5 MB
__device__ float g_Vt[BB*HH*SS*DD];   // 67 MB

// Q'[b,h,s,i] = q[b,s,h,i] * fc(s,i); same for K'.
// fc(s,i) = 2 * (s * theta^(-i/64)); the *2 is exact (power of two),
// inv computed in double then rounded -> matches fp32 reference to ~1ulp.
__global__ void prep_qk(const float* __restrict__ q, const float* __restrict__ k) {
    int tid = blockIdx.x * blockDim.x + threadIdx.x;
    if (tid >= BB*HH*SS*DH) return;
    int i = tid & 63;
    int s = (tid >> 6) & 2047;
    int h = (tid >> 17) & 15;
    int b = tid >> 21;
    float inv = (float)exp(-(double)i * (9.210340371976184 / 64.0)); // ln(1e4)/64
    float fc = 2.0f * ((float)s * inv);
    int gin = ((b*SS + s)*HH + h)*DD + i;
    g_Qp[tid] = q[gin] * fc;
    g_Kp[tid] = k[gin] * fc;
}

__global__ void prep_v(const float* __restrict__ v) {
    int tid = blockIdx.x * blockDim.x + threadIdx.x;
    if (tid >= BB*HH*SS*DD) return;
    int d = tid & 127;
    int s = (tid >> 7) & 2047;
    int h = (tid >> 18) & 15;
    int b = tid >> 22;
    g_Vt[tid] = v[((b*SS + s)*HH + h)*DD + d];
}

// Flash-attention tile kernel: BM=64 queries x full key loop (BN=64 tiles).
// 256 threads: GEMM1 (64x64, 4x4 micro), GEMM2 (64x128, 4x8 micro).
__global__ __launch_bounds__(256, 2)
void attn_kernel(float* __restrict__ out) {
    extern __shared__ float sm[];
    float* Qs  = sm;                 // 64 x 65
    float* Ks  = Qs + BM*65;         // 64 x 65
    float* Ps  = Ks + BN*65;         // 64 x 65
    float* Vs  = Ps + BM*65;         // 64 x 128 (16B-aligned: 12480 floats before)
    float* mrow = Vs + BN*DD;        // 64
    float* lrow = mrow + BM;         // 64
    float* facr = lrow + BM;         // 64
    float* mnew = facr + BM;         // 64

    const int qt = blockIdx.x, h = blockIdx.y, b = blockIdx.z;
    const int tid = threadIdx.x;
    const int ti = tid >> 4;         // 0..15
    const int tj = tid & 15;         // 0..15

    const float* Qg  = g_Qp + (((b*HH + h)*SS) + qt*BM)*DH;
    const float* Kg0 = g_Kp + ((b*HH + h)*SS)*DH;
    const float* Vg0 = g_Vt + ((b*HH + h)*SS)*DD;

    // Load Q tile once
    for (int idx = tid; idx < BM*DH; idx += 256) {
        int r = idx >> 6, c = idx & 63;
        Qs[r*65 + c] = Qg[idx];
    }
    if (tid < BM) { mrow[tid] = -INFINITY; lrow[tid] = 0.0f; }

    float o[4][8];
    #pragma unroll
    for (int rx = 0; rx < 4; rx++)
        #pragma unroll
        for (int c = 0; c < 8; c++) o[rx][c] = 0.0f;

    for (int kt = 0; kt < SS/BN; ++kt) {
        __syncthreads();   // prev iteration fully done with Ks/Vs/Ps; Qs ready on iter 0

        // Load K' and V tiles
        const float* Kg = Kg0 + kt*BN*DH;
        for (int idx = tid; idx < BN*DH; idx += 256) {
            int r = idx >> 6, c = idx & 63;
            Ks[r*65 + c] = Kg[idx];
        }
        {
            const float4* Vg = (const float4*)(Vg0 + kt*BN*DD);
            float4* Vs4 = (float4*)Vs;
            for (int idx = tid; idx < BN*DD/4; idx += 256) Vs4[idx] = Vg[idx];
        }
        __syncthreads();

        // GEMM1: S = Q' K'^T  (scaled by 1/64)
        float acc[4][4];
        #pragma unroll
        for (int rx = 0; rx < 4; rx++)
            #pragma unroll
            for (int cx = 0; cx < 4; cx++) acc[rx][cx] = 0.0f;

        #pragma unroll 16
        for (int kk = 0; kk < DH; ++kk) {
            float a[4], bb[4];
            #pragma unroll
            for (int x = 0; x < 4; x++) a[x]  = Qs[(ti*4 + x)*65 + kk];
            #pragma unroll
            for (int x = 0; x < 4; x++) bb[x] = Ks[(tj*4 + x)*65 + kk];
            #pragma unroll
            for (int rx = 0; rx < 4; rx++)
                #pragma unroll
                for (int cx = 0; cx < 4; cx++)
                    acc[rx][cx] += a[rx] * bb[cx];
        }
        const float sc = 1.0f / 64.0f;   // exact power-of-two scale (== 2/128)
        #pragma unroll
        for (int rx = 0; rx < 4; rx++)
            #pragma unroll
            for (int cx = 0; cx < 4; cx++)
                Ps[(ti*4 + rx)*65 + tj*4 + cx] = acc[rx][cx] * sc;
        __syncthreads();

        // Row max + online-softmax factors
        if (tid < BM) {
            float mx = -INFINITY;
            for (int j = 0; j < BN; j++) mx = fmaxf(mx, Ps[tid*65 + j]);
            float mo = mrow[tid];
            float mn = fmaxf(mo, mx);
            mrow[tid] = mn;
            mnew[tid] = mn;
            facr[tid] = expf(mo - mn);   // expf(-inf)=0 on first tile
        }
        __syncthreads();

        // P = exp(S - m_new) in place; rescale O by factor
        #pragma unroll
        for (int rx = 0; rx < 4; rx++) {
            int r = ti*4 + rx;
            float mn = mnew[r];
            #pragma unroll
            for (int cx = 0; cx < 4; cx++) {
                int idx = r*65 + tj*4 + cx;
                Ps[idx] = expf(Ps[idx] - mn);
            }
            float f = facr[r];
            #pragma unroll
            for (int c = 0; c < 8; c++) o[rx][c] *= f;
        }
        __syncthreads();

        // l update (reads only; overlaps with GEMM2 reads)
        if (tid < BM) {
            float sum = 0.0f;
            for (int j = 0; j < BN; j++) sum += Ps[tid*65 + j];
            lrow[tid] = lrow[tid]*facr[tid] + sum;
        }

        // GEMM2: O += P V
        #pragma unroll 8
        for (int kk = 0; kk < BN; ++kk) {
            float a[4];
            #pragma unroll
            for (int rx = 0; rx < 4; rx++) a[rx] = Ps[(ti*4 + rx)*65 + kk];
            float4 v0 = *(const float4*)&Vs[kk*DD + tj*8];
            float4 v1 = *(const float4*)&Vs[kk*DD + tj*8 + 4];
            #pragma unroll
            for (int rx = 0; rx < 4; rx++) {
                o[rx][0] += a[rx]*v0.x;  o[rx][1] += a[rx]*v0.y;
                o[rx][2] += a[rx]*v0.z;  o[rx][3] += a[rx]*v0.w;
                o[rx][4] += a[rx]*v1.x;  o[rx][5] += a[rx]*v1.y;
                o[rx][6] += a[rx]*v1.z;  o[rx][7] += a[rx]*v1.w;
            }
        }
    }
    __syncthreads();

    // Normalize and write: out[(b*S+s)*H*D + h*D + d]
    #pragma unroll
    for (int rx = 0; rx < 4; rx++) {
        int srow = qt*BM + ti*4 + rx;
        float inv_l = 1.0f / lrow[ti*4 + rx];
        float* op = out + (((size_t)b*SS + srow)*HH + h)*DD + tj*8;
        float4 w0, w1;
        w0.x = o[rx][0]*inv_l; w0.y = o[rx][1]*inv_l;
        w0.z = o[rx][2]*inv_l; w0.w = o[rx][3]*inv_l;
        w1.x = o[rx][4]*inv_l; w1.y = o[rx][5]*inv_l;
        w1.z = o[rx][6]*inv_l; w1.w = o[rx][7]*inv_l;
        *(float4*)op = w0;
        *(float4*)(op + 4) = w1;
    }
}

extern "C" void kernel_launch(void* const* d_in, const int* in_sizes, int n_in,
                              void* d_out, int out_size) {
    const float* q = (const float*)d_in[0];
    const float* k = (const float*)d_in[1];
    const float* v = (const float*)d_in[2];
    float* out = (float*)d_out;

    const int smem = (3*BM*65 + BN*DD + 4*BM) * (int)sizeof(float);  // 83712 B
    cudaFuncSetAttribute(attn_kernel, cudaFuncAttributeMaxDynamicSharedMemorySize, smem);

    prep_qk<<<(BB*HH*SS*DH + 255)/256, 256>>>(q, k);
    prep_v<<<(BB*HH*SS*DD + 255)/256, 256>>>(v);

    dim3 grid(SS/BM, HH, BB);
    attn_kernel<<<grid, 256, smem>>>(out);
}